// round 2
// baseline (speedup 1.0000x reference)
#include <cuda_runtime.h>
#include <cuda_bf16.h>

// Problem constants
#define NN 20000
#define EE 320000
#define DD 256
#define GG 128

// ---------------- device scratch (static, no allocation) ----------------
__device__ float g_bufA[NN * DD];       // 20.48 MB
__device__ float g_bufB[NN * DD];       // 20.48 MB
__device__ int   g_cnt[NN];
__device__ int   g_fill[NN];
__device__ int   g_rowptr[NN + 1];
__device__ float g_dis[NN];
__device__ int   g_csr_src[EE];
__device__ float g_csr_norm[EE];
__device__ int   g_is64;                // 1 if edge_index/batch are int64

// Buffer selection (avoids any host-side symbol-address API)
__device__ __forceinline__ float* buf(int which) {
    return which ? g_bufB : g_bufA;
}

// ---------------- index dtype handling ----------------
__device__ __forceinline__ int load_idx(const void* p, int i) {
    if (g_is64) return (int)((const long long*)p)[i];
    return ((const int*)p)[i];
}

// Detect whether indices are int64 or int32. If int32 data (random indices in
// [0,20000)) is reinterpreted as int64, values are astronomically out of range
// almost surely within 256 samples.
__global__ void detect_kernel(const void* ei) {
    bool ok64 = true;
    const long long* p = (const long long*)ei;
    for (int i = 0; i < 256; i++) {
        long long v = p[i];
        if (v < 0 || v >= NN) { ok64 = false; break; }
    }
    g_is64 = ok64 ? 1 : 0;
}

// ---------------- CSR build ----------------
__global__ void init_kernel() {
    int i = blockIdx.x * blockDim.x + threadIdx.x;
    if (i < NN) { g_cnt[i] = 0; g_fill[i] = 0; }
}

__global__ void count_kernel(const void* ei) {
    int e = blockIdx.x * blockDim.x + threadIdx.x;
    if (e < EE) {
        int d = load_idx(ei, EE + e);   // dst row
        atomicAdd(&g_cnt[d], 1);
    }
}

// Single-block exclusive scan of g_cnt -> g_rowptr; also dis = rsqrt(deg)
__global__ void scan_kernel() {
    __shared__ int sh[1024];
    int tid = threadIdx.x;
    int running = 0;
    for (int base = 0; base < NN; base += 1024) {
        int i = base + tid;
        int v = (i < NN) ? g_cnt[i] : 0;
        sh[tid] = v;
        __syncthreads();
        for (int off = 1; off < 1024; off <<= 1) {
            int t = (tid >= off) ? sh[tid - off] : 0;
            __syncthreads();
            sh[tid] += t;
            __syncthreads();
        }
        if (i < NN) {
            g_rowptr[i] = running + sh[tid] - v;         // exclusive prefix
            g_dis[i]    = rsqrtf((float)(v + 1));        // +1 self loop
        }
        int tot = sh[1023];
        __syncthreads();
        running += tot;
    }
    if (tid == 0) g_rowptr[NN] = running;
}

__global__ void fill_kernel(const void* ei) {
    int e = blockIdx.x * blockDim.x + threadIdx.x;
    if (e < EE) {
        int s = load_idx(ei, e);
        int d = load_idx(ei, EE + e);
        int p = atomicAdd(&g_fill[d], 1);
        int o = g_rowptr[d] + p;
        g_csr_src[o]  = s;
        g_csr_norm[o] = g_dis[s] * g_dis[d];
    }
}

// ---------------- GEMM: C[M,256] = A[M,256] @ B[256,256] (+bias) ----------------
// 128x128 tile, 256 threads, 8x8 per thread, K-chunk 16.
// a_sel: -1 = external A (x input), 0/1 = g_bufA/g_bufB. c_sel: 0/1.
__global__ __launch_bounds__(256) void gemm_kernel(
    const float* __restrict__ Aext, int a_sel, const float* __restrict__ B,
    const float* __restrict__ bias, int c_sel, int M)
{
    const float* A = (a_sel < 0) ? Aext : buf(a_sel);
    float* C = buf(c_sel);

    __shared__ float As[16][128];   // [k][m] (A transposed in smem)
    __shared__ float Bs[16][128];   // [k][n]

    int tx = threadIdx.x & 15;      // 0..15 -> 8 cols each
    int ty = threadIdx.x >> 4;      // 0..15 -> 8 rows each
    int m0 = blockIdx.y * 128;
    int n0 = blockIdx.x * 128;

    float acc[8][8];
#pragma unroll
    for (int i = 0; i < 8; i++)
#pragma unroll
        for (int j = 0; j < 8; j++) acc[i][j] = 0.0f;

    for (int k0 = 0; k0 < 256; k0 += 16) {
        // Load A tile 128x16 -> As[k][m]
        {
            int t = threadIdx.x;
            int r = t >> 1;               // row in tile 0..127
            int c = (t & 1) * 8;          // col base 0 or 8
            int gm = m0 + r;
            float4 v0, v1;
            if (gm < M) {
                const float* ap = &A[(size_t)gm * 256 + k0 + c];
                v0 = *(const float4*)(ap);
                v1 = *(const float4*)(ap + 4);
            } else {
                v0 = make_float4(0.f, 0.f, 0.f, 0.f);
                v1 = v0;
            }
            As[c + 0][r] = v0.x; As[c + 1][r] = v0.y;
            As[c + 2][r] = v0.z; As[c + 3][r] = v0.w;
            As[c + 4][r] = v1.x; As[c + 5][r] = v1.y;
            As[c + 6][r] = v1.z; As[c + 7][r] = v1.w;
        }
        // Load B tile 16x128 -> Bs[k][n]
        {
            int t = threadIdx.x;
            int r = t >> 4;               // 0..15
            int c = (t & 15) * 8;         // 0..120
            const float* bp = &B[(size_t)(k0 + r) * 256 + n0 + c];
            *(float4*)&Bs[r][c]     = *(const float4*)(bp);
            *(float4*)&Bs[r][c + 4] = *(const float4*)(bp + 4);
        }
        __syncthreads();

#pragma unroll
        for (int kk = 0; kk < 16; kk++) {
            float a[8], b[8];
            *(float4*)&a[0] = *(const float4*)&As[kk][ty * 8];
            *(float4*)&a[4] = *(const float4*)&As[kk][ty * 8 + 4];
            *(float4*)&b[0] = *(const float4*)&Bs[kk][tx * 8];
            *(float4*)&b[4] = *(const float4*)&Bs[kk][tx * 8 + 4];
#pragma unroll
            for (int i = 0; i < 8; i++)
#pragma unroll
                for (int j = 0; j < 8; j++)
                    acc[i][j] = fmaf(a[i], b[j], acc[i][j]);
        }
        __syncthreads();
    }

#pragma unroll
    for (int i = 0; i < 8; i++) {
        int gm = m0 + ty * 8 + i;
        if (gm < M) {
#pragma unroll
            for (int j = 0; j < 8; j += 4) {
                int gn = n0 + tx * 8 + j;
                float4 v = make_float4(acc[i][j], acc[i][j + 1],
                                       acc[i][j + 2], acc[i][j + 3]);
                if (bias) {
                    v.x += bias[gn];     v.y += bias[gn + 1];
                    v.z += bias[gn + 2]; v.w += bias[gn + 3];
                }
                *(float4*)&C[(size_t)gm * 256 + gn] = v;
            }
        }
    }
}

// ---------------- Aggregation (gather by dst via CSR) ----------------
// mode 0: out = relu(agg + bias)
// mode 1: out += agg + bias            (out pre-holds residual)
__global__ __launch_bounds__(256) void agg_kernel(
    int h_sel, const float* __restrict__ bias, int o_sel, int mode)
{
    const float* h = buf(h_sel);
    float* out = buf(o_sel);

    int node = blockIdx.x * 4 + (threadIdx.x >> 6);
    int lane = threadIdx.x & 63;
    if (node >= NN) return;

    const float4* h4 = (const float4*)h;
    float di = g_dis[node];
    float w0 = di * di;                     // self-loop weight
    float4 acc = h4[(size_t)node * 64 + lane];
    acc.x *= w0; acc.y *= w0; acc.z *= w0; acc.w *= w0;

    int beg = g_rowptr[node], end = g_rowptr[node + 1];
    for (int j = beg; j < end; j++) {
        int   s = g_csr_src[j];
        float w = g_csr_norm[j];
        float4 v = h4[(size_t)s * 64 + lane];
        acc.x = fmaf(v.x, w, acc.x);
        acc.y = fmaf(v.y, w, acc.y);
        acc.z = fmaf(v.z, w, acc.z);
        acc.w = fmaf(v.w, w, acc.w);
    }

    float4 bb = ((const float4*)bias)[lane];
    float4* o4 = (float4*)out;
    size_t oi = (size_t)node * 64 + lane;
    if (mode == 0) {
        float4 r;
        r.x = fmaxf(acc.x + bb.x, 0.f);
        r.y = fmaxf(acc.y + bb.y, 0.f);
        r.z = fmaxf(acc.z + bb.z, 0.f);
        r.w = fmaxf(acc.w + bb.w, 0.f);
        o4[oi] = r;
    } else {
        float4 cur = o4[oi];
        cur.x += acc.x + bb.x;
        cur.y += acc.y + bb.y;
        cur.z += acc.z + bb.z;
        cur.w += acc.w + bb.w;
        o4[oi] = cur;
    }
}

// ---------------- Mean pooling (batch sorted -> binary search ranges) ----------------
__global__ void pool_kernel(int s_sel, const void* __restrict__ batch,
                            float* __restrict__ out)
{
    const float* s = buf(s_sel);
    int g = blockIdx.x;
    int t = threadIdx.x;     // 256 threads, one per feature
    __shared__ int sh[2];
    if (t < 2) {
        int target = g + t;
        int lo = 0, hi = NN;
        while (lo < hi) {
            int mid = (lo + hi) >> 1;
            if (load_idx(batch, mid) < target) lo = mid + 1; else hi = mid;
        }
        sh[t] = lo;
    }
    __syncthreads();
    int lo = sh[0], hi = sh[1];
    float acc = 0.0f;
    for (int i = lo; i < hi; i++) acc += s[(size_t)i * 256 + t];
    int cnt = hi - lo;
    out[(size_t)g * 256 + t] = acc / (float)(cnt > 0 ? cnt : 1);
}

// ---------------- launch ----------------
extern "C" void kernel_launch(void* const* d_in, const int* in_sizes, int n_in,
                              void* d_out, int out_size)
{
    const float* x    = (const float*)d_in[0];
    const float* W1   = (const float*)d_in[1];
    const float* b1   = (const float*)d_in[2];
    const float* W2   = (const float*)d_in[3];
    const float* b2   = (const float*)d_in[4];
    const float* Wlin = (const float*)d_in[5];
    const float* blin = (const float*)d_in[6];
    const void*  ei   = d_in[7];
    const void*  batch= d_in[8];
    float* out = (float*)d_out;

    detect_kernel<<<1, 1>>>(ei);
    init_kernel<<<(NN + 255) / 256, 256>>>();
    count_kernel<<<(EE + 255) / 256, 256>>>(ei);
    scan_kernel<<<1, 1024>>>();
    fill_kernel<<<(EE + 255) / 256, 256>>>(ei);

    dim3 ggrid(2, (NN + 127) / 128);      // 2 x 157 tiles
    // h1 = x @ W1                      -> bufA
    gemm_kernel<<<ggrid, 256>>>(x, -1, W1, nullptr, 0, NN);
    // x1 = relu(agg(h1) + b1)          -> bufB
    agg_kernel<<<(NN + 3) / 4, 256>>>(0, b1, 1, 0);
    // h2 = x1 @ W2                     -> bufA
    gemm_kernel<<<ggrid, 256>>>(nullptr, 1, W2, nullptr, 0, NN);
    // res = x @ Wlin + blin            -> bufB
    gemm_kernel<<<ggrid, 256>>>(x, -1, Wlin, blin, 1, NN);
    // s = res + agg(h2) + b2           -> bufB
    agg_kernel<<<(NN + 3) / 4, 256>>>(0, b2, 1, 1);
    // mean pool per graph
    pool_kernel<<<GG, 256>>>(1, batch, out);
}

// round 3
// speedup vs baseline: 1.2891x; 1.2891x over previous
#include <cuda_runtime.h>
#include <cstdint>

// Problem constants
#define NN 20000
#define EE 320000
#define DD 256
#define GG 128

// ---------------- device scratch (static, no allocation) ----------------
__device__ float g_bufA[NN * DD];       // 20.48 MB
__device__ float g_bufB[NN * DD];       // 20.48 MB
__device__ int   g_cnt[NN];
__device__ int   g_fill[NN];
__device__ int   g_rowptr[NN + 1];
__device__ float g_dis[NN];
__device__ int   g_csr_src[EE];
__device__ float g_csr_norm[EE];
__device__ int   g_is64;                // 1 if edge_index/batch are int64

__device__ __forceinline__ float* buf(int which) {
    return which ? g_bufB : g_bufA;
}

// ---------------- index dtype handling ----------------
__device__ __forceinline__ int load_idx(const void* p, int i) {
    if (g_is64) return (int)((const long long*)p)[i];
    return ((const int*)p)[i];
}

__global__ void detect_kernel(const void* ei) {
    bool ok64 = true;
    const long long* p = (const long long*)ei;
    for (int i = 0; i < 256; i++) {
        long long v = p[i];
        if (v < 0 || v >= NN) { ok64 = false; break; }
    }
    g_is64 = ok64 ? 1 : 0;
}

// ---------------- CSR build ----------------
__global__ void init_kernel() {
    int i = blockIdx.x * blockDim.x + threadIdx.x;
    if (i < NN) { g_cnt[i] = 0; g_fill[i] = 0; }
}

__global__ void count_kernel(const void* ei) {
    int e = blockIdx.x * blockDim.x + threadIdx.x;
    if (e < EE) {
        int d = load_idx(ei, EE + e);
        atomicAdd(&g_cnt[d], 1);
    }
}

// Single-pass scan: 1024 threads x 20 elements each, shfl-based.
__global__ void scan_kernel() {
    const int CH = 20;                  // 1024*20 = 20480 >= NN
    int tid  = threadIdx.x;
    int lane = tid & 31, w = tid >> 5;
    int base = tid * CH;

    int cnt[CH], ex[CH];
    int s = 0;
#pragma unroll
    for (int i = 0; i < CH; i++) {
        int idx = base + i;
        int c = (idx < NN) ? g_cnt[idx] : 0;
        cnt[i] = c; ex[i] = s; s += c;
    }
    // warp inclusive scan of per-thread sums
    int x = s;
#pragma unroll
    for (int o = 1; o < 32; o <<= 1) {
        int y = __shfl_up_sync(0xffffffffu, x, o);
        if (lane >= o) x += y;
    }
    __shared__ int wsum[32];
    if (lane == 31) wsum[w] = x;
    int wex = x - s;                    // exclusive within warp
    __syncthreads();
    if (w == 0) {
        int v = wsum[lane];
        int xx = v;
#pragma unroll
        for (int o = 1; o < 32; o <<= 1) {
            int y = __shfl_up_sync(0xffffffffu, xx, o);
            if (lane >= o) xx += y;
        }
        wsum[lane] = xx - v;            // exclusive warp offsets
    }
    __syncthreads();
    int off = wsum[w] + wex;
#pragma unroll
    for (int i = 0; i < CH; i++) {
        int idx = base + i;
        if (idx < NN) {
            g_rowptr[idx] = off + ex[i];
            g_dis[idx]    = rsqrtf((float)(cnt[i] + 1));   // +1 self loop
        }
    }
    if (tid == 0) g_rowptr[NN] = EE;    // all dst valid -> total is always EE
}

__global__ void fill_kernel(const void* ei) {
    int e = blockIdx.x * blockDim.x + threadIdx.x;
    if (e < EE) {
        int s = load_idx(ei, e);
        int d = load_idx(ei, EE + e);
        int p = atomicAdd(&g_fill[d], 1);
        int o = g_rowptr[d] + p;
        g_csr_src[o]  = s;
        g_csr_norm[o] = g_dis[s] * g_dis[d];
    }
}

// ---------------- Tensor-core GEMM (3xTF32): C[M,256] = A[M,256] @ B[256,256] ----------------
__device__ __forceinline__ uint32_t f2tf(float x) {
    uint32_t r; asm("cvt.rna.tf32.f32 %0, %1;" : "=r"(r) : "f"(x)); return r;
}
__device__ __forceinline__ void mma8(float* c,
    uint32_t a0, uint32_t a1, uint32_t a2, uint32_t a3, uint32_t b0, uint32_t b1)
{
    asm volatile(
        "mma.sync.aligned.m16n8k8.row.col.f32.tf32.tf32.f32 "
        "{%0,%1,%2,%3}, {%4,%5,%6,%7}, {%8,%9}, {%0,%1,%2,%3};"
        : "+f"(c[0]), "+f"(c[1]), "+f"(c[2]), "+f"(c[3])
        : "r"(a0), "r"(a1), "r"(a2), "r"(a3), "r"(b0), "r"(b1));
}

#define APAD 36     // floats per A smem row: mod32=4 -> conflict-free frag LDS, float4-aligned
#define BPAD 136    // floats per B smem row: mod32=8 -> conflict-free frag LDS, float4-aligned

// Block tile 128x128, BK=32, 8 warps (4 M x 2 N), warp tile 32x64.
__global__ __launch_bounds__(256) void gemm_tc(
    const float* __restrict__ Aext, int a_sel, const float* __restrict__ B,
    const float* __restrict__ bias, int c_sel, int M)
{
    const float* A = (a_sel < 0) ? Aext : buf(a_sel);
    float* C = buf(c_sel);

    __shared__ float As[128 * APAD];    // 18.4 KB
    __shared__ float Bs[32 * BPAD];     // 17.4 KB

    int tid = threadIdx.x;
    int lane = tid & 31, warp = tid >> 5;
    int g = lane >> 2, t = lane & 3;    // mma group / thread-in-group
    int warp_m = warp >> 1, warp_n = warp & 1;
    int m0 = blockIdx.y * 128, n0 = blockIdx.x * 128;

    float c[2][8][4];
#pragma unroll
    for (int mt = 0; mt < 2; mt++)
#pragma unroll
        for (int nt = 0; nt < 8; nt++)
#pragma unroll
            for (int i = 0; i < 4; i++) c[mt][nt][i] = 0.0f;

    for (int k0 = 0; k0 < 256; k0 += 32) {
        // A tile 128x32
#pragma unroll
        for (int i = 0; i < 4; i++) {
            int idx = i * 256 + tid;            // 0..1023 float4 slots
            int r = idx >> 3, c4 = (idx & 7) * 4;
            int gm = m0 + r;
            float4 v = make_float4(0.f, 0.f, 0.f, 0.f);
            if (gm < M) v = *(const float4*)&A[(size_t)gm * 256 + k0 + c4];
            *(float4*)&As[r * APAD + c4] = v;
        }
        // B tile 32x128
#pragma unroll
        for (int i = 0; i < 4; i++) {
            int idx = i * 256 + tid;
            int r = idx >> 5, c4 = (idx & 31) * 4;
            float4 v = *(const float4*)&B[(size_t)(k0 + r) * 256 + n0 + c4];
            *(float4*)&Bs[r * BPAD + c4] = v;
        }
        __syncthreads();

#pragma unroll
        for (int k8 = 0; k8 < 32; k8 += 8) {
            uint32_t ahi[2][4], alo[2][4];
#pragma unroll
            for (int mt = 0; mt < 2; mt++) {
                int r0 = warp_m * 32 + mt * 16 + g;
                float a0 = As[r0 * APAD + k8 + t];
                float a1 = As[(r0 + 8) * APAD + k8 + t];
                float a2 = As[r0 * APAD + k8 + t + 4];
                float a3 = As[(r0 + 8) * APAD + k8 + t + 4];
                ahi[mt][0] = f2tf(a0); alo[mt][0] = f2tf(a0 - __uint_as_float(ahi[mt][0]));
                ahi[mt][1] = f2tf(a1); alo[mt][1] = f2tf(a1 - __uint_as_float(ahi[mt][1]));
                ahi[mt][2] = f2tf(a2); alo[mt][2] = f2tf(a2 - __uint_as_float(ahi[mt][2]));
                ahi[mt][3] = f2tf(a3); alo[mt][3] = f2tf(a3 - __uint_as_float(ahi[mt][3]));
            }
#pragma unroll
            for (int nt = 0; nt < 8; nt++) {
                int col = warp_n * 64 + nt * 8 + g;
                float b0 = Bs[(k8 + t) * BPAD + col];
                float b1 = Bs[(k8 + t + 4) * BPAD + col];
                uint32_t bh0 = f2tf(b0), bh1 = f2tf(b1);
                uint32_t bl0 = f2tf(b0 - __uint_as_float(bh0));
                uint32_t bl1 = f2tf(b1 - __uint_as_float(bh1));
#pragma unroll
                for (int mt = 0; mt < 2; mt++) {
                    mma8(c[mt][nt], ahi[mt][0], ahi[mt][1], ahi[mt][2], ahi[mt][3], bh0, bh1);
                    mma8(c[mt][nt], alo[mt][0], alo[mt][1], alo[mt][2], alo[mt][3], bh0, bh1);
                    mma8(c[mt][nt], ahi[mt][0], ahi[mt][1], ahi[mt][2], ahi[mt][3], bl0, bl1);
                }
            }
        }
        __syncthreads();
    }

    // store (float2 per row-half, bias optional)
#pragma unroll
    for (int mt = 0; mt < 2; mt++) {
#pragma unroll
        for (int nt = 0; nt < 8; nt++) {
            int gn = n0 + warp_n * 64 + nt * 8 + 2 * t;
            float bx = 0.f, by = 0.f;
            if (bias) { bx = bias[gn]; by = bias[gn + 1]; }
            int gm0 = m0 + warp_m * 32 + mt * 16 + g;
            if (gm0 < M)
                *(float2*)&C[(size_t)gm0 * 256 + gn] =
                    make_float2(c[mt][nt][0] + bx, c[mt][nt][1] + by);
            int gm1 = gm0 + 8;
            if (gm1 < M)
                *(float2*)&C[(size_t)gm1 * 256 + gn] =
                    make_float2(c[mt][nt][2] + bx, c[mt][nt][3] + by);
        }
    }
}

// ---------------- Aggregation (gather by dst via CSR) ----------------
// mode 0: out = relu(agg + bias)
// mode 1: out += agg + bias            (out pre-holds residual)
__global__ __launch_bounds__(256) void agg_kernel(
    int h_sel, const float* __restrict__ bias, int o_sel, int mode)
{
    const float* h = buf(h_sel);
    float* out = buf(o_sel);

    int node = blockIdx.x * 4 + (threadIdx.x >> 6);
    int lane = threadIdx.x & 63;
    if (node >= NN) return;

    const float4* h4 = (const float4*)h;
    float di = g_dis[node];
    float w0 = di * di;                     // self-loop weight
    float4 acc = h4[(size_t)node * 64 + lane];
    acc.x *= w0; acc.y *= w0; acc.z *= w0; acc.w *= w0;

    int beg = g_rowptr[node], end = g_rowptr[node + 1];
    for (int j = beg; j < end; j++) {
        int   s = g_csr_src[j];
        float w = g_csr_norm[j];
        float4 v = h4[(size_t)s * 64 + lane];
        acc.x = fmaf(v.x, w, acc.x);
        acc.y = fmaf(v.y, w, acc.y);
        acc.z = fmaf(v.z, w, acc.z);
        acc.w = fmaf(v.w, w, acc.w);
    }

    float4 bb = ((const float4*)bias)[lane];
    float4* o4 = (float4*)out;
    size_t oi = (size_t)node * 64 + lane;
    if (mode == 0) {
        float4 r;
        r.x = fmaxf(acc.x + bb.x, 0.f);
        r.y = fmaxf(acc.y + bb.y, 0.f);
        r.z = fmaxf(acc.z + bb.z, 0.f);
        r.w = fmaxf(acc.w + bb.w, 0.f);
        o4[oi] = r;
    } else {
        float4 cur = o4[oi];
        cur.x += acc.x + bb.x;
        cur.y += acc.y + bb.y;
        cur.z += acc.z + bb.z;
        cur.w += acc.w + bb.w;
        o4[oi] = cur;
    }
}

// ---------------- Mean pooling (batch sorted -> binary search ranges) ----------------
__global__ void pool_kernel(int s_sel, const void* __restrict__ batch,
                            float* __restrict__ out)
{
    const float* s = buf(s_sel);
    int g = blockIdx.x;
    int t = threadIdx.x;     // 256 threads, one per feature
    __shared__ int sh[2];
    if (t < 2) {
        int target = g + t;
        int lo = 0, hi = NN;
        while (lo < hi) {
            int mid = (lo + hi) >> 1;
            if (load_idx(batch, mid) < target) lo = mid + 1; else hi = mid;
        }
        sh[t] = lo;
    }
    __syncthreads();
    int lo = sh[0], hi = sh[1];
    float acc = 0.0f;
    for (int i = lo; i < hi; i++) acc += s[(size_t)i * 256 + t];
    int cnt = hi - lo;
    out[(size_t)g * 256 + t] = acc / (float)(cnt > 0 ? cnt : 1);
}

// ---------------- launch ----------------
extern "C" void kernel_launch(void* const* d_in, const int* in_sizes, int n_in,
                              void* d_out, int out_size)
{
    const float* x    = (const float*)d_in[0];
    const float* W1   = (const float*)d_in[1];
    const float* b1   = (const float*)d_in[2];
    const float* W2   = (const float*)d_in[3];
    const float* b2   = (const float*)d_in[4];
    const float* Wlin = (const float*)d_in[5];
    const float* blin = (const float*)d_in[6];
    const void*  ei   = d_in[7];
    const void*  batch= d_in[8];
    float* out = (float*)d_out;

    detect_kernel<<<1, 1>>>(ei);
    init_kernel<<<(NN + 255) / 256, 256>>>();
    count_kernel<<<(EE + 255) / 256, 256>>>(ei);
    scan_kernel<<<1, 1024>>>();
    fill_kernel<<<(EE + 255) / 256, 256>>>(ei);

    dim3 ggrid(2, (NN + 127) / 128);      // 2 x 157 tiles
    // h1 = x @ W1                      -> bufA
    gemm_tc<<<ggrid, 256>>>(x, -1, W1, nullptr, 0, NN);
    // x1 = relu(agg(h1) + b1)          -> bufB
    agg_kernel<<<(NN + 3) / 4, 256>>>(0, b1, 1, 0);
    // h2 = x1 @ W2                     -> bufA
    gemm_tc<<<ggrid, 256>>>(nullptr, 1, W2, nullptr, 0, NN);
    // res = x @ Wlin + blin            -> bufB
    gemm_tc<<<ggrid, 256>>>(x, -1, Wlin, blin, 1, NN);
    // s = res + agg(h2) + b2           -> bufB
    agg_kernel<<<(NN + 3) / 4, 256>>>(0, b2, 1, 1);
    // mean pool per graph
    pool_kernel<<<GG, 256>>>(1, batch, out);
}

// round 4
// speedup vs baseline: 2.0412x; 1.5834x over previous
#include <cuda_runtime.h>
#include <cstdint>

// Problem constants
#define NN 20000
#define EE 320000
#define DD 256
#define GG 128

// ---------------- device scratch (static, no allocation) ----------------
__device__ float g_bufA[NN * DD];       // 20.48 MB
__device__ float g_bufB[NN * DD];       // 20.48 MB
__device__ int   g_cnt[NN];
__device__ int   g_fill[NN];
__device__ int   g_rowptr[NN + 1];
__device__ float g_dis[NN];
__device__ int   g_csr_src[EE];
__device__ float g_csr_norm[EE];
__device__ int   g_is64;                // 1 if edge_index/batch are int64
__device__ float g_yg[GG * DD];         // mean-pooled A*x1
__device__ float g_px[GG * DD];         // mean-pooled x
__device__ int   g_gcnt[GG];

__device__ __forceinline__ float* buf(int which) {
    return which ? g_bufB : g_bufA;
}

// ---------------- index dtype handling ----------------
__device__ __forceinline__ int load_idx(const void* p, int i) {
    if (g_is64) return (int)((const long long*)p)[i];
    return ((const int*)p)[i];
}

// Parallel dtype probe: 256 samples, one per thread.
__global__ void detect_kernel(const void* ei) {
    __shared__ int bad;
    if (threadIdx.x == 0) bad = 0;
    __syncthreads();
    long long v = ((const long long*)ei)[threadIdx.x];
    if (v < 0 || v >= NN) bad = 1;
    __syncthreads();
    if (threadIdx.x == 0) g_is64 = bad ? 0 : 1;
}

// ---------------- CSR build ----------------
__global__ void init_kernel() {
    int i = blockIdx.x * blockDim.x + threadIdx.x;
    if (i < NN) { g_cnt[i] = 0; g_fill[i] = 0; }
}

__global__ void count_kernel(const void* ei) {
    int e = blockIdx.x * blockDim.x + threadIdx.x;
    if (e < EE) {
        int d = load_idx(ei, EE + e);
        atomicAdd(&g_cnt[d], 1);
    }
}

// Coalesced single-block scan: 20 tiles of 1024, shfl warp scan + warp0 combine.
__global__ void scan_kernel() {
    __shared__ int wsum[32];
    __shared__ int carry_s;
    int tid = threadIdx.x, lane = tid & 31, w = tid >> 5;
    if (tid == 0) carry_s = 0;
    __syncthreads();

    for (int base = 0; base < NN; base += 1024) {
        int i = base + tid;
        int v = (i < NN) ? g_cnt[i] : 0;
        int x = v;
#pragma unroll
        for (int o = 1; o < 32; o <<= 1) {
            int y = __shfl_up_sync(0xffffffffu, x, o);
            if (lane >= o) x += y;
        }
        if (lane == 31) wsum[w] = x;
        __syncthreads();
        if (w == 0) {
            int s = wsum[lane];
            int xx = s;
#pragma unroll
            for (int o = 1; o < 32; o <<= 1) {
                int y = __shfl_up_sync(0xffffffffu, xx, o);
                if (lane >= o) xx += y;
            }
            wsum[lane] = xx - s;        // exclusive warp offsets
        }
        __syncthreads();
        int carry = carry_s;
        if (i < NN) {
            g_rowptr[i] = carry + wsum[w] + x - v;
            g_dis[i]    = rsqrtf((float)(v + 1));   // +1 self loop
        }
        __syncthreads();
        if (tid == 1023) carry_s = carry + wsum[31] + x;   // block total
        __syncthreads();
    }
    if (tid == 0) g_rowptr[NN] = EE;    // all dst valid -> total always EE
}

__global__ void fill_kernel(const void* ei) {
    int e = blockIdx.x * blockDim.x + threadIdx.x;
    if (e < EE) {
        int s = load_idx(ei, e);
        int d = load_idx(ei, EE + e);
        int p = atomicAdd(&g_fill[d], 1);
        int o = g_rowptr[d] + p;
        g_csr_src[o]  = s;
        g_csr_norm[o] = g_dis[s] * g_dis[d];
    }
}

// ---------------- Tensor-core GEMM (3xTF32): C[M,256] = A[M,256] @ B[256,256] ----------------
__device__ __forceinline__ uint32_t f2tf(float x) {
    uint32_t r; asm("cvt.rna.tf32.f32 %0, %1;" : "=r"(r) : "f"(x)); return r;
}
__device__ __forceinline__ void mma8(float* c,
    uint32_t a0, uint32_t a1, uint32_t a2, uint32_t a3, uint32_t b0, uint32_t b1)
{
    asm volatile(
        "mma.sync.aligned.m16n8k8.row.col.f32.tf32.tf32.f32 "
        "{%0,%1,%2,%3}, {%4,%5,%6,%7}, {%8,%9}, {%0,%1,%2,%3};"
        : "+f"(c[0]), "+f"(c[1]), "+f"(c[2]), "+f"(c[3])
        : "r"(a0), "r"(a1), "r"(a2), "r"(a3), "r"(b0), "r"(b1));
}

#define APAD 36
#define BPAD 136

__global__ __launch_bounds__(256) void gemm_tc(
    const float* __restrict__ Aext, int a_sel, const float* __restrict__ B,
    const float* __restrict__ bias, int c_sel, int M)
{
    const float* A = (a_sel < 0) ? Aext : buf(a_sel);
    float* C = buf(c_sel);

    __shared__ float As[128 * APAD];
    __shared__ float Bs[32 * BPAD];

    int tid = threadIdx.x;
    int lane = tid & 31, warp = tid >> 5;
    int g = lane >> 2, t = lane & 3;
    int warp_m = warp >> 1, warp_n = warp & 1;
    int m0 = blockIdx.y * 128, n0 = blockIdx.x * 128;

    float c[2][8][4];
#pragma unroll
    for (int mt = 0; mt < 2; mt++)
#pragma unroll
        for (int nt = 0; nt < 8; nt++)
#pragma unroll
            for (int i = 0; i < 4; i++) c[mt][nt][i] = 0.0f;

    for (int k0 = 0; k0 < 256; k0 += 32) {
#pragma unroll
        for (int i = 0; i < 4; i++) {
            int idx = i * 256 + tid;
            int r = idx >> 3, c4 = (idx & 7) * 4;
            int gm = m0 + r;
            float4 v = make_float4(0.f, 0.f, 0.f, 0.f);
            if (gm < M) v = *(const float4*)&A[(size_t)gm * 256 + k0 + c4];
            *(float4*)&As[r * APAD + c4] = v;
        }
#pragma unroll
        for (int i = 0; i < 4; i++) {
            int idx = i * 256 + tid;
            int r = idx >> 5, c4 = (idx & 31) * 4;
            float4 v = *(const float4*)&B[(size_t)(k0 + r) * 256 + n0 + c4];
            *(float4*)&Bs[r * BPAD + c4] = v;
        }
        __syncthreads();

#pragma unroll
        for (int k8 = 0; k8 < 32; k8 += 8) {
            uint32_t ahi[2][4], alo[2][4];
#pragma unroll
            for (int mt = 0; mt < 2; mt++) {
                int r0 = warp_m * 32 + mt * 16 + g;
                float a0 = As[r0 * APAD + k8 + t];
                float a1 = As[(r0 + 8) * APAD + k8 + t];
                float a2 = As[r0 * APAD + k8 + t + 4];
                float a3 = As[(r0 + 8) * APAD + k8 + t + 4];
                ahi[mt][0] = f2tf(a0); alo[mt][0] = f2tf(a0 - __uint_as_float(ahi[mt][0]));
                ahi[mt][1] = f2tf(a1); alo[mt][1] = f2tf(a1 - __uint_as_float(ahi[mt][1]));
                ahi[mt][2] = f2tf(a2); alo[mt][2] = f2tf(a2 - __uint_as_float(ahi[mt][2]));
                ahi[mt][3] = f2tf(a3); alo[mt][3] = f2tf(a3 - __uint_as_float(ahi[mt][3]));
            }
#pragma unroll
            for (int nt = 0; nt < 8; nt++) {
                int col = warp_n * 64 + nt * 8 + g;
                float b0 = Bs[(k8 + t) * BPAD + col];
                float b1 = Bs[(k8 + t + 4) * BPAD + col];
                uint32_t bh0 = f2tf(b0), bh1 = f2tf(b1);
                uint32_t bl0 = f2tf(b0 - __uint_as_float(bh0));
                uint32_t bl1 = f2tf(b1 - __uint_as_float(bh1));
#pragma unroll
                for (int mt = 0; mt < 2; mt++) {
                    mma8(c[mt][nt], ahi[mt][0], ahi[mt][1], ahi[mt][2], ahi[mt][3], bh0, bh1);
                    mma8(c[mt][nt], alo[mt][0], alo[mt][1], alo[mt][2], alo[mt][3], bh0, bh1);
                    mma8(c[mt][nt], ahi[mt][0], ahi[mt][1], ahi[mt][2], ahi[mt][3], bl0, bl1);
                }
            }
        }
        __syncthreads();
    }

#pragma unroll
    for (int mt = 0; mt < 2; mt++) {
#pragma unroll
        for (int nt = 0; nt < 8; nt++) {
            int gn = n0 + warp_n * 64 + nt * 8 + 2 * t;
            float bx = 0.f, by = 0.f;
            if (bias) { bx = bias[gn]; by = bias[gn + 1]; }
            int gm0 = m0 + warp_m * 32 + mt * 16 + g;
            if (gm0 < M)
                *(float2*)&C[(size_t)gm0 * 256 + gn] =
                    make_float2(c[mt][nt][0] + bx, c[mt][nt][1] + by);
            int gm1 = gm0 + 8;
            if (gm1 < M)
                *(float2*)&C[(size_t)gm1 * 256 + gn] =
                    make_float2(c[mt][nt][2] + bx, c[mt][nt][3] + by);
        }
    }
}

// ---------------- Aggregation (gather by dst via CSR) ----------------
// mode 0: out = relu(agg + bias)
// mode 2: out = agg                 (raw, for pooled second layer)
__global__ __launch_bounds__(256) void agg_kernel(
    int h_sel, const float* __restrict__ bias, int o_sel, int mode)
{
    const float* h = buf(h_sel);
    float* out = buf(o_sel);

    int node = blockIdx.x * 4 + (threadIdx.x >> 6);
    int lane = threadIdx.x & 63;
    if (node >= NN) return;

    const float4* h4 = (const float4*)h;
    float di = g_dis[node];
    float w0 = di * di;                     // self-loop weight
    float4 acc = h4[(size_t)node * 64 + lane];
    acc.x *= w0; acc.y *= w0; acc.z *= w0; acc.w *= w0;

    int beg = g_rowptr[node], end = g_rowptr[node + 1];
    for (int j = beg; j < end; j++) {
        int   s = g_csr_src[j];
        float w = g_csr_norm[j];
        float4 v = h4[(size_t)s * 64 + lane];
        acc.x = fmaf(v.x, w, acc.x);
        acc.y = fmaf(v.y, w, acc.y);
        acc.z = fmaf(v.z, w, acc.z);
        acc.w = fmaf(v.w, w, acc.w);
    }

    float4* o4 = (float4*)out;
    size_t oi = (size_t)node * 64 + lane;
    if (mode == 0) {
        float4 bb = ((const float4*)bias)[lane];
        float4 r;
        r.x = fmaxf(acc.x + bb.x, 0.f);
        r.y = fmaxf(acc.y + bb.y, 0.f);
        r.z = fmaxf(acc.z + bb.z, 0.f);
        r.w = fmaxf(acc.w + bb.w, 0.f);
        o4[oi] = r;
    } else {
        o4[oi] = acc;
    }
}

// ---------------- Fused dual mean-pool: yg = mean(z), px = mean(x) per graph ----------------
__global__ void pool2_kernel(int z_sel, const float* __restrict__ x,
                             const void* __restrict__ batch)
{
    const float* z = buf(z_sel);
    int g = blockIdx.x;
    int t = threadIdx.x;     // 256 threads, one per feature
    __shared__ int sh[2];
    if (t < 2) {
        int target = g + t;
        int lo = 0, hi = NN;
        while (lo < hi) {
            int mid = (lo + hi) >> 1;
            if (load_idx(batch, mid) < target) lo = mid + 1; else hi = mid;
        }
        sh[t] = lo;
    }
    __syncthreads();
    int lo = sh[0], hi = sh[1];
    float az = 0.0f, ax = 0.0f;
    for (int i = lo; i < hi; i++) {
        az += z[(size_t)i * 256 + t];
        ax += x[(size_t)i * 256 + t];
    }
    int cnt = hi - lo;
    float inv = 1.0f / (float)(cnt > 0 ? cnt : 1);
    g_yg[g * 256 + t] = az * inv;
    g_px[g * 256 + t] = ax * inv;
    if (t == 0) g_gcnt[g] = cnt;
}

// ---------------- Final tiny GEMM: out[g] = yg[g]@W2 + px[g]@Wlin + b2 + blin ----------------
__global__ __launch_bounds__(256) void final_kernel(
    const float* __restrict__ W2, const float* __restrict__ b2,
    const float* __restrict__ Wlin, const float* __restrict__ blin,
    float* __restrict__ out)
{
    int g = blockIdx.x, c = threadIdx.x;
    __shared__ float ys[256], ps[256];
    ys[c] = g_yg[g * 256 + c];
    ps[c] = g_px[g * 256 + c];
    __syncthreads();
    float acc = 0.0f;
#pragma unroll 8
    for (int k = 0; k < 256; k++) {
        acc = fmaf(ys[k], W2[k * 256 + c], acc);
        acc = fmaf(ps[k], Wlin[k * 256 + c], acc);
    }
    int cnt = g_gcnt[g];
    out[(size_t)g * 256 + c] = (cnt > 0) ? (acc + b2[c] + blin[c]) : 0.0f;
}

// ---------------- launch ----------------
extern "C" void kernel_launch(void* const* d_in, const int* in_sizes, int n_in,
                              void* d_out, int out_size)
{
    const float* x    = (const float*)d_in[0];
    const float* W1   = (const float*)d_in[1];
    const float* b1   = (const float*)d_in[2];
    const float* W2   = (const float*)d_in[3];
    const float* b2   = (const float*)d_in[4];
    const float* Wlin = (const float*)d_in[5];
    const float* blin = (const float*)d_in[6];
    const void*  ei   = d_in[7];
    const void*  batch= d_in[8];
    float* out = (float*)d_out;

    detect_kernel<<<1, 256>>>(ei);
    init_kernel<<<(NN + 255) / 256, 256>>>();
    count_kernel<<<(EE + 255) / 256, 256>>>(ei);
    scan_kernel<<<1, 1024>>>();
    fill_kernel<<<(EE + 255) / 256, 256>>>(ei);

    dim3 ggrid(2, (NN + 127) / 128);
    // h1 = x @ W1                      -> bufA
    gemm_tc<<<ggrid, 256>>>(x, -1, W1, nullptr, 0, NN);
    // x1 = relu(agg(h1) + b1)          -> bufB
    agg_kernel<<<(NN + 3) / 4, 256>>>(0, b1, 1, 0);
    // z = agg(x1)  (raw A*x1)          -> bufA
    agg_kernel<<<(NN + 3) / 4, 256>>>(1, b1, 0, 2);
    // yg = meanpool(z), px = meanpool(x)
    pool2_kernel<<<GG, 256>>>(0, x, batch);
    // out = yg@W2 + px@Wlin + b2 + blin
    final_kernel<<<GG, 256>>>(W2, b2, Wlin, blin, out);
}